// round 1
// baseline (speedup 1.0000x reference)
#include <cuda_runtime.h>

// LIF neuron scan: x[B=64, S=1024, F=512] fp32 -> spikes (0/1) fp32 same shape.
// m_{t} = 0.95*m_{t-1} + x_t ; s_t = (m_t > 0.5) ; m_t = s_t ? 0 : m_t
// Chains are independent across (b, f): 32768 serial chains of length 1024.
// Pure HBM-bound streaming problem: 128 MB in + 128 MB out.

#define LIF_B 64
#define LIF_S 1024
#define LIF_F 512
#define LIF_U 16          // time unroll: 16 independent loads in flight per thread
#define LIF_THREADS 128   // 256 blocks over 148 SMs (blockDim 256 would strand 20 SMs)

__global__ __launch_bounds__(LIF_THREADS)
void lif_scan_kernel(const float* __restrict__ x, float* __restrict__ out) {
    const int tid = blockIdx.x * LIF_THREADS + threadIdx.x;  // 0..32767
    const int b = tid >> 9;          // tid / 512
    const int f = tid & (LIF_F - 1); // tid % 512
    // base of this chain; step t advances by F floats (2 KB). Lane-adjacent f
    // => one coalesced 128B line per warp per time step, load and store.
    size_t base = (size_t)b * (LIF_S * LIF_F) + (size_t)f;

    float m = 0.0f;

    #pragma unroll 1
    for (int t = 0; t < LIF_S; t += LIF_U) {
        // Front-batch the loads: addresses do not depend on m, so all LIF_U
        // LDGs issue back-to-back (MLP = 16 lines/thread-batch).
        float xv[LIF_U];
        #pragma unroll
        for (int u = 0; u < LIF_U; u++) {
            xv[u] = __ldcs(x + base + (size_t)(t + u) * LIF_F);
        }

        // Serial recurrence (cheap FMA/SEL chain), buffer spikes.
        float sv[LIF_U];
        #pragma unroll
        for (int u = 0; u < LIF_U; u++) {
            m = fmaf(0.95f, m, xv[u]);
            const bool fire = (m > 0.5f);
            sv[u] = fire ? 1.0f : 0.0f;
            m = fire ? 0.0f : m;
        }

        // Streaming stores, coalesced per time step.
        #pragma unroll
        for (int u = 0; u < LIF_U; u++) {
            __stcs(out + base + (size_t)(t + u) * LIF_F, sv[u]);
        }
    }
}

extern "C" void kernel_launch(void* const* d_in, const int* in_sizes, int n_in,
                              void* d_out, int out_size) {
    (void)in_sizes; (void)n_in; (void)out_size;
    const float* x = (const float*)d_in[0];
    float* out = (float*)d_out;
    const int total_threads = LIF_B * LIF_F;                 // 32768 chains
    const int blocks = total_threads / LIF_THREADS;          // 256
    lif_scan_kernel<<<blocks, LIF_THREADS>>>(x, out);
}

// round 4
// speedup vs baseline: 1.3201x; 1.3201x over previous
#include <cuda_runtime.h>

// LIF neuron scan: x[B=64, S=1024, F=512] fp32 -> spikes (0/1) fp32.
// m = 0.95*m + x_t ; s = (m > 0.5) ; m = s ? 0 : m
// 32768 independent chains (one per (b,f)), serial only in time.
// HBM-bound: 128 MB read + 128 MB write.
// R1: DRAM 38.9% => latency-bound (~55 lines/SM in flight vs ~190 needed).
// Fix: U=32 + ping-pong double buffer so ~32 loads/warp stay outstanding
// through compute+store. (R2/R3 were broker container failures; resubmit.)

#define LIF_B 64
#define LIF_S 1024
#define LIF_F 512
#define LIF_U 32          // loads in flight per buffer
#define LIF_THREADS 128   // 256 blocks over 148 SMs

__device__ __forceinline__ void lif_prefetch(float* __restrict__ buf,
                                             const float* __restrict__ xp) {
    #pragma unroll
    for (int u = 0; u < LIF_U; u++)
        buf[u] = __ldcs(xp + u * LIF_F);
}

__device__ __forceinline__ void lif_compute_store(const float* __restrict__ xv,
                                                  float& m,
                                                  float* __restrict__ op) {
    float sv[LIF_U];
    #pragma unroll
    for (int u = 0; u < LIF_U; u++) {
        m = fmaf(0.95f, m, xv[u]);
        const bool fire = (m > 0.5f);
        sv[u] = fire ? 1.0f : 0.0f;
        m = fire ? 0.0f : m;
    }
    #pragma unroll
    for (int u = 0; u < LIF_U; u++)
        __stcs(op + u * LIF_F, sv[u]);
}

__global__ __launch_bounds__(LIF_THREADS)
void lif_scan_kernel(const float* __restrict__ x, float* __restrict__ out) {
    const int tid = blockIdx.x * LIF_THREADS + threadIdx.x;  // 0..32767
    const int b = tid >> 9;          // / 512
    const int f = tid & (LIF_F - 1); // % 512
    const int base = b * (LIF_S * LIF_F) + f;   // < 2^25, fits int

    const float* xp = x + base;
    float* op = out + base;

    float m = 0.0f;
    float bufA[LIF_U], bufB[LIF_U];

    lif_prefetch(bufA, xp);  // t = [0, U)

    // 1024 / (2*32) = 16 outer iterations, no tail.
    #pragma unroll 1
    for (int it = 0; it < LIF_S / (2 * LIF_U); it++) {
        // Prefetch next half-batch BEFORE consuming the current one:
        // keeps ~32 lines/warp outstanding through compute + store.
        lif_prefetch(bufB, xp + LIF_U * LIF_F);
        lif_compute_store(bufA, m, op);

        if (it + 1 < LIF_S / (2 * LIF_U))
            lif_prefetch(bufA, xp + 2 * LIF_U * LIF_F);
        lif_compute_store(bufB, m, op + LIF_U * LIF_F);

        xp += 2 * LIF_U * LIF_F;
        op += 2 * LIF_U * LIF_F;
    }
}

extern "C" void kernel_launch(void* const* d_in, const int* in_sizes, int n_in,
                              void* d_out, int out_size) {
    (void)in_sizes; (void)n_in; (void)out_size;
    const float* x = (const float*)d_in[0];
    float* out = (float*)d_out;
    const int total_threads = LIF_B * LIF_F;        // 32768 chains
    const int blocks = total_threads / LIF_THREADS; // 256
    lif_scan_kernel<<<blocks, LIF_THREADS>>>(x, out);
}

// round 5
// speedup vs baseline: 1.5212x; 1.1523x over previous
#include <cuda_runtime.h>
#include <cstdint>

// LIF neuron scan: x[B=64, S=1024, F=512] fp32 -> spikes (0/1) fp32.
// m = 0.95*m + x_t ; s = (m > 0.5) ; m = s ? 0 : m
// 32768 independent chains. HBM-bound: 128 MB in + 128 MB out.
// R4: register double-buffer hit DRAM 52.4% — MLP is coupled to the 12cyc/step
// serial chain (loads idle during compute/store). Fix: cp.async -> smem
// 4-stage pipeline; in-flight bytes (2 stages = 32KB/block = 256 lines)
// decoupled from registers and from chain timing.

#define LIF_B 64
#define LIF_S 1024
#define LIF_F 512
#define LIF_CH 32                       // time steps per stage
#define LIF_NSTAGE 4
#define LIF_THREADS 128
#define LIF_STAGE_FLOATS (LIF_CH * LIF_THREADS)           // 4096 floats = 16KB
#define LIF_SMEM_BYTES (LIF_NSTAGE * LIF_STAGE_FLOATS * 4) // 64KB

__device__ __forceinline__ void cp_async16(uint32_t dst, const float* src) {
    asm volatile("cp.async.cg.shared.global [%0], [%1], 16;\n"
                 :: "r"(dst), "l"(src));
}
__device__ __forceinline__ void cp_commit() {
    asm volatile("cp.async.commit_group;\n" ::: "memory");
}
template <int N>
__device__ __forceinline__ void cp_wait() {
    asm volatile("cp.async.wait_group %0;\n" :: "n"(N) : "memory");
}

// Fill stage `st` with time steps [t0, t0+CH). Warp w loads full 512B rows
// (step = k*4 + w, lane = 16B chunk) -> perfectly coalesced, no registers.
__device__ __forceinline__ void lif_fill(uint32_t sm_base, const float* __restrict__ xb,
                                         int st, int t0, int w, int lane) {
    const uint32_t sdst = sm_base + (uint32_t)(st * LIF_STAGE_FLOATS) * 4u;
    #pragma unroll
    for (int k = 0; k < 8; k++) {
        const int c = k * 4 + w;  // step within stage, warp-uniform
        cp_async16(sdst + (uint32_t)(c * LIF_THREADS + lane * 4) * 4u,
                   xb + (size_t)(t0 + c) * LIF_F + lane * 4);
    }
}

__global__ __launch_bounds__(LIF_THREADS)
void lif_scan_kernel(const float* __restrict__ x, float* __restrict__ out) {
    extern __shared__ float sm[];
    const int tid = threadIdx.x;
    const int w = tid >> 5;
    const int lane = tid & 31;

    // Block covers 128 consecutive chains (same b; f0..f0+127): 512B/step rows.
    const int chain0 = blockIdx.x * LIF_THREADS;
    const int b = chain0 >> 9;           // / 512
    const int f0 = chain0 & (LIF_F - 1); // % 512
    const float* xb = x + (size_t)b * LIF_S * LIF_F + f0;
    float* op = out + (size_t)b * LIF_S * LIF_F + f0 + tid;  // this thread's column

    const uint32_t sm_base = (uint32_t)__cvta_generic_to_shared(sm);

    // Prologue: stages 0..2 in flight.
    #pragma unroll
    for (int s = 0; s < LIF_NSTAGE - 1; s++) {
        lif_fill(sm_base, xb, s, s * LIF_CH, w, lane);
        cp_commit();
    }

    float m = 0.0f;
    const int NIT = LIF_S / LIF_CH;  // 32 stages total

    #pragma unroll 1
    for (int s = 0; s < NIT; s++) {
        // Issue next fill (keeps 2 stages outstanding through compute+store).
        if (s + LIF_NSTAGE - 1 < NIT)
            lif_fill(sm_base, xb, (s + LIF_NSTAGE - 1) % LIF_NSTAGE,
                     (s + LIF_NSTAGE - 1) * LIF_CH, w, lane);
        cp_commit();                 // one group per iteration (empty ok at tail)
        cp_wait<LIF_NSTAGE - 2>();   // stage s complete
        __syncthreads();             // smem written by other warps

        const float* stage = sm + (s % LIF_NSTAGE) * LIF_STAGE_FLOATS;

        float xv[LIF_CH];
        #pragma unroll
        for (int c = 0; c < LIF_CH; c++)
            xv[c] = stage[c * LIF_THREADS + tid];   // conflict-free LDS

        float sv[LIF_CH];
        #pragma unroll
        for (int c = 0; c < LIF_CH; c++) {
            m = fmaf(0.95f, m, xv[c]);
            const bool fire = (m > 0.5f);
            sv[c] = fire ? 1.0f : 0.0f;
            m = fire ? 0.0f : m;
        }

        float* o = op + (size_t)s * LIF_CH * LIF_F;
        #pragma unroll
        for (int c = 0; c < LIF_CH; c++)
            __stcs(o + (size_t)c * LIF_F, sv[c]);

        __syncthreads();  // all reads done before this buffer is refilled (iter s+1)
    }
}

extern "C" void kernel_launch(void* const* d_in, const int* in_sizes, int n_in,
                              void* d_out, int out_size) {
    (void)in_sizes; (void)n_in; (void)out_size;
    const float* x = (const float*)d_in[0];
    float* out = (float*)d_out;

    static bool attr_set = false;  // idempotent host-side attribute, not work
    if (!attr_set) {
        cudaFuncSetAttribute(lif_scan_kernel,
                             cudaFuncAttributeMaxDynamicSharedMemorySize,
                             LIF_SMEM_BYTES);
        attr_set = true;
    }

    const int blocks = (LIF_B * LIF_F) / LIF_THREADS;  // 256
    lif_scan_kernel<<<blocks, LIF_THREADS, LIF_SMEM_BYTES>>>(x, out);
}